// round 12
// baseline (speedup 1.0000x reference)
#include <cuda_runtime.h>
#include <cuda_bf16.h>
#include <cstdint>

#define NN   50000
#define F_IN 256
#define HID  128
#define NH   8
#define EE   800000
#define MM   3
#define OUTD 8
#define SEGS (MM * NN)
#define CK   32   // K-chunk
#define ASTR 40   // padded smem row stride (halves)

// ---------------- scratch (device globals; no allocation) ----------------
__device__ float d_h [NN * HID];
__device__ float d_fs[(size_t)MM * NN * HID];
__device__ float d_el[(size_t)MM * NN * NH];
__device__ float d_er[(size_t)MM * NN * NH];
__device__ float d_vd[MM * NH * HID];
__device__ float d_z [(size_t)NN * MM * HID];
__device__ float d_w [NN * MM];
__device__ int   d_cnt [SEGS];
__device__ int   d_off [SEGS];
__device__ int   d_pos [SEGS];
__device__ int   d_ssrc[MM * EE];
// B' transposed weights, [128][2K]: [n][0..K)=hi, [n][K..2K)=lo
__device__ __nv_bfloat16 d_Bfc[128 * 2 * F_IN];
__device__ __nv_bfloat16 d_Bpr[MM * 128 * 2 * HID];
__device__ __nv_bfloat16 d_Bsm[128 * 2 * HID];

__device__ __forceinline__ float elu1(float v)
{
    return v > 0.f ? v : (__expf(v) - 1.f);
}

__device__ __forceinline__ uint32_t smem_u32(const void* p) {
    uint32_t a;
    asm("{ .reg .u64 t; cvta.to.shared.u64 t, %1; cvt.u32.u64 %0, t; }"
        : "=r"(a) : "l"(p));
    return a;
}

// ---------------- unified prep: all weight splits + Vdst in ONE launch ------
// blockIdx.y: 0 = W_fc->d_Bfc (K=256); 1..3 = W_src[m]->d_Bpr (K=128);
//             4 = W_sem1->d_Bsm (K=128); 5 = vdst
__global__ void prep_all(const float* __restrict__ W_fc,
                         const float* __restrict__ W_src,
                         const float* __restrict__ W_sem1,
                         const float* __restrict__ W_dst,
                         const float* __restrict__ ar)
{
    int y = blockIdx.y;
    int t = blockIdx.x * blockDim.x + threadIdx.x;
    if (y == 5) {
        if (t >= MM * NH * HID) return;
        int m = t / (NH * HID);
        int r = t - m * (NH * HID);
        int h = r / HID;
        int k = r - h * HID;
        const float* W = W_dst + ((size_t)m * HID + k) * HID + h * 16;
        const float* a = ar + (m * NH + h) * 16;
        float s = 0.f;
#pragma unroll
        for (int d = 0; d < 16; d++) s += W[d] * a[d];
        d_vd[(m * NH + h) * HID + k] = s;
        return;
    }
    const float* W;
    __nv_bfloat16* Bp;
    int K;
    if (y == 0)      { W = W_fc;   Bp = d_Bfc; K = F_IN; }
    else if (y <= 3) { int m = y - 1; W = W_src + (size_t)m * HID * HID;
                       Bp = d_Bpr + (size_t)m * 128 * 2 * HID; K = HID; }
    else             { W = W_sem1; Bp = d_Bsm; K = HID; }
    if (t >= 128 * K) return;
    int k = t >> 7;
    int n = t & 127;
    float v = W[(size_t)k * 128 + n];
    __nv_bfloat16 h = __float2bfloat16(v);
    __nv_bfloat16 l = __float2bfloat16(v - __bfloat162float(h));
    size_t base = (size_t)n * 2 * K;
    Bp[base + k]     = h;
    Bp[base + K + k] = l;
}

// ---------------- tensor-core GEMM via mma.sync, bf16 hi/lo split -----------
// D = Ah@Bh + Ah@Bl + Al@Bh  (fp32 accum); tile 128x128, 8 warps (2x4)
// mode 0: C = A@W + bias     mode 1 (grid.y=m): C = A@W ; el head-dots fused
// mode 2: A'=elu(A); wout = tanh(A'@W + bias) . w2  (no C store)
__global__ void __launch_bounds__(256) mgemm(
    const float* __restrict__ A, const __nv_bfloat16* __restrict__ Bp,
    const float* __restrict__ bias, float* __restrict__ Cb,
    const float* __restrict__ att, float* __restrict__ elb,
    const float* __restrict__ w2, float* __restrict__ wout,
    int Mrows, int K, int mode)
{
    __shared__ __nv_bfloat16 Ah[128 * ASTR];
    __shared__ __nv_bfloat16 Al[128 * ASTR];
    __shared__ __nv_bfloat16 Bh[128 * ASTR];
    __shared__ __nv_bfloat16 Bl[128 * ASTR];
    __shared__ float redbuf[128];

    const int tid = threadIdx.x;
    const int lane = tid & 31;
    const int wid = tid >> 5;
    const int warp_m = wid >> 2;      // 0..1 -> rows warp_m*64
    const int warp_n = wid & 3;       // 0..3 -> cols warp_n*32
    const int rowBase = blockIdx.x * 128;

    const __nv_bfloat16* B = Bp;
    float* C = Cb; const float* av = att; float* eo = elb;
    if (mode == 1) {
        int m = blockIdx.y;
        B  += (size_t)m * 128 * 2 * K;
        C  += (size_t)m * NN * HID;
        av += (size_t)m * HID;
        eo += (size_t)m * NN * NH;
    }

    float cfr[4][4][4];
#pragma unroll
    for (int mt = 0; mt < 4; mt++)
#pragma unroll
        for (int nt = 0; nt < 4; nt++)
#pragma unroll
            for (int q = 0; q < 4; q++) cfr[mt][nt][q] = 0.f;

    // loader mapping: row = tid>>1, 16-wide half-chunk = (tid&1)*16
    const int lrow = tid >> 1;
    const int lcol = (tid & 1) * 16;
    const bool aok = (rowBase + lrow) < Mrows;
    const float* Arow = A + (size_t)(rowBase + lrow) * K;
    const __nv_bfloat16* Bh_row = B + (size_t)lrow * 2 * K;
    const __nv_bfloat16* Bl_row = Bh_row + K;

    const uint32_t ahb = smem_u32(Ah);
    const uint32_t alb = smem_u32(Al);
    const uint32_t bhb = smem_u32(Bh);
    const uint32_t blb = smem_u32(Bl);

    for (int kc = 0; kc < K; kc += CK) {
        // ---- load A chunk fp32 -> hi/lo bf16 ----
        {
            uint32_t* dh = reinterpret_cast<uint32_t*>(&Ah[lrow * ASTR + lcol]);
            uint32_t* dl = reinterpret_cast<uint32_t*>(&Al[lrow * ASTR + lcol]);
#pragma unroll
            for (int q = 0; q < 4; q++) {
                float4 v = aok ? *reinterpret_cast<const float4*>(Arow + kc + lcol + q * 4)
                               : make_float4(0.f, 0.f, 0.f, 0.f);
                if (mode == 2) { v.x = elu1(v.x); v.y = elu1(v.y); v.z = elu1(v.z); v.w = elu1(v.w); }
                __nv_bfloat16 h0 = __float2bfloat16(v.x);
                __nv_bfloat16 h1 = __float2bfloat16(v.y);
                __nv_bfloat16 h2 = __float2bfloat16(v.z);
                __nv_bfloat16 h3 = __float2bfloat16(v.w);
                __nv_bfloat16 l0 = __float2bfloat16(v.x - __bfloat162float(h0));
                __nv_bfloat16 l1 = __float2bfloat16(v.y - __bfloat162float(h1));
                __nv_bfloat16 l2 = __float2bfloat16(v.z - __bfloat162float(h2));
                __nv_bfloat16 l3 = __float2bfloat16(v.w - __bfloat162float(h3));
                __nv_bfloat162 hp0 = __halves2bfloat162(h0, h1);
                __nv_bfloat162 hp1 = __halves2bfloat162(h2, h3);
                __nv_bfloat162 lp0 = __halves2bfloat162(l0, l1);
                __nv_bfloat162 lp1 = __halves2bfloat162(l2, l3);
                dh[q * 2]     = *reinterpret_cast<uint32_t*>(&hp0);
                dh[q * 2 + 1] = *reinterpret_cast<uint32_t*>(&hp1);
                dl[q * 2]     = *reinterpret_cast<uint32_t*>(&lp0);
                dl[q * 2 + 1] = *reinterpret_cast<uint32_t*>(&lp1);
            }
        }
        // ---- load B hi/lo chunks (pre-split, straight copy) ----
        {
            const uint4* gh = reinterpret_cast<const uint4*>(Bh_row + kc + lcol);
            const uint4* gl = reinterpret_cast<const uint4*>(Bl_row + kc + lcol);
            uint4* dh = reinterpret_cast<uint4*>(&Bh[lrow * ASTR + lcol]);
            uint4* dl = reinterpret_cast<uint4*>(&Bl[lrow * ASTR + lcol]);
            dh[0] = gh[0]; dh[1] = gh[1];
            dl[0] = gl[0]; dl[1] = gl[1];
        }
        __syncthreads();

        // ---- 2 k-steps of 16 ----
#pragma unroll
        for (int ks = 0; ks < 2; ks++) {
            int k0 = ks * 16;
            int ra = warp_m * 64 + (lane & 15);
            int ka = k0 + (lane >> 4) * 8;
            int nb = warp_n * 32 + (lane & 7);
            int kb = k0 + ((lane >> 3) & 1) * 8;

            uint32_t ah[4][4], bh[4][2], bl[4][2];
#pragma unroll
            for (int mt = 0; mt < 4; mt++) {
                uint32_t addr = ahb + (uint32_t)((ra + mt * 16) * ASTR + ka) * 2u;
                asm volatile("ldmatrix.sync.aligned.m8n8.x4.shared.b16 {%0,%1,%2,%3}, [%4];"
                             : "=r"(ah[mt][0]), "=r"(ah[mt][1]), "=r"(ah[mt][2]), "=r"(ah[mt][3])
                             : "r"(addr));
            }
#pragma unroll
            for (int nt = 0; nt < 4; nt++) {
                uint32_t addr = bhb + (uint32_t)((nb + nt * 8) * ASTR + kb) * 2u;
                asm volatile("ldmatrix.sync.aligned.m8n8.x2.shared.b16 {%0,%1}, [%2];"
                             : "=r"(bh[nt][0]), "=r"(bh[nt][1]) : "r"(addr));
                uint32_t addr2 = blb + (uint32_t)((nb + nt * 8) * ASTR + kb) * 2u;
                asm volatile("ldmatrix.sync.aligned.m8n8.x2.shared.b16 {%0,%1}, [%2];"
                             : "=r"(bl[nt][0]), "=r"(bl[nt][1]) : "r"(addr2));
            }
#pragma unroll
            for (int mt = 0; mt < 4; mt++)
#pragma unroll
                for (int nt = 0; nt < 4; nt++) {
                    asm volatile(
                        "mma.sync.aligned.m16n8k16.row.col.f32.bf16.bf16.f32 "
                        "{%0,%1,%2,%3}, {%4,%5,%6,%7}, {%8,%9}, {%0,%1,%2,%3};"
                        : "+f"(cfr[mt][nt][0]), "+f"(cfr[mt][nt][1]),
                          "+f"(cfr[mt][nt][2]), "+f"(cfr[mt][nt][3])
                        : "r"(ah[mt][0]), "r"(ah[mt][1]), "r"(ah[mt][2]), "r"(ah[mt][3]),
                          "r"(bh[nt][0]), "r"(bh[nt][1]));
                    asm volatile(
                        "mma.sync.aligned.m16n8k16.row.col.f32.bf16.bf16.f32 "
                        "{%0,%1,%2,%3}, {%4,%5,%6,%7}, {%8,%9}, {%0,%1,%2,%3};"
                        : "+f"(cfr[mt][nt][0]), "+f"(cfr[mt][nt][1]),
                          "+f"(cfr[mt][nt][2]), "+f"(cfr[mt][nt][3])
                        : "r"(ah[mt][0]), "r"(ah[mt][1]), "r"(ah[mt][2]), "r"(ah[mt][3]),
                          "r"(bl[nt][0]), "r"(bl[nt][1]));
                }
            // A_lo frags after hi frags retire (register pressure)
            uint32_t al4[4][4];
#pragma unroll
            for (int mt = 0; mt < 4; mt++) {
                uint32_t addr = alb + (uint32_t)((ra + mt * 16) * ASTR + ka) * 2u;
                asm volatile("ldmatrix.sync.aligned.m8n8.x4.shared.b16 {%0,%1,%2,%3}, [%4];"
                             : "=r"(al4[mt][0]), "=r"(al4[mt][1]), "=r"(al4[mt][2]), "=r"(al4[mt][3])
                             : "r"(addr));
            }
#pragma unroll
            for (int mt = 0; mt < 4; mt++)
#pragma unroll
                for (int nt = 0; nt < 4; nt++) {
                    asm volatile(
                        "mma.sync.aligned.m16n8k16.row.col.f32.bf16.bf16.f32 "
                        "{%0,%1,%2,%3}, {%4,%5,%6,%7}, {%8,%9}, {%0,%1,%2,%3};"
                        : "+f"(cfr[mt][nt][0]), "+f"(cfr[mt][nt][1]),
                          "+f"(cfr[mt][nt][2]), "+f"(cfr[mt][nt][3])
                        : "r"(al4[mt][0]), "r"(al4[mt][1]), "r"(al4[mt][2]), "r"(al4[mt][3]),
                          "r"(bh[nt][0]), "r"(bh[nt][1]));
                }
        }
        __syncthreads();
    }

    // ---- epilogues ----
    const int g = lane >> 2, j = lane & 3;

    if (mode == 0 || mode == 1) {
#pragma unroll
        for (int mt = 0; mt < 4; mt++) {
            int r1 = rowBase + warp_m * 64 + mt * 16 + g;
            int r2 = r1 + 8;
#pragma unroll
            for (int nt = 0; nt < 4; nt++) {
                int c = warp_n * 32 + nt * 8 + j * 2;
                float b0 = 0.f, b1 = 0.f;
                if (mode == 0) { b0 = bias[c]; b1 = bias[c + 1]; }
                if (r1 < Mrows)
                    *reinterpret_cast<float2*>(C + (size_t)r1 * HID + c) =
                        make_float2(cfr[mt][nt][0] + b0, cfr[mt][nt][1] + b1);
                if (r2 < Mrows)
                    *reinterpret_cast<float2*>(C + (size_t)r2 * HID + c) =
                        make_float2(cfr[mt][nt][2] + b0, cfr[mt][nt][3] + b1);
            }
            if (mode == 1) {
                float p1[2] = {0.f, 0.f}, p2[2] = {0.f, 0.f};
#pragma unroll
                for (int nt = 0; nt < 4; nt++) {
                    int hl = nt >> 1;
                    int c = warp_n * 32 + nt * 8 + j * 2;
                    float a0 = av[c], a1 = av[c + 1];
                    p1[hl] += cfr[mt][nt][0] * a0 + cfr[mt][nt][1] * a1;
                    p2[hl] += cfr[mt][nt][2] * a0 + cfr[mt][nt][3] * a1;
                }
#pragma unroll
                for (int hl = 0; hl < 2; hl++) {
                    p1[hl] += __shfl_xor_sync(0xffffffffu, p1[hl], 1);
                    p1[hl] += __shfl_xor_sync(0xffffffffu, p1[hl], 2);
                    p2[hl] += __shfl_xor_sync(0xffffffffu, p2[hl], 1);
                    p2[hl] += __shfl_xor_sync(0xffffffffu, p2[hl], 2);
                }
                if (j == 0) {
                    int h0 = warp_n * 2;
                    if (r1 < Mrows) {
                        eo[(size_t)r1 * NH + h0]     = p1[0];
                        eo[(size_t)r1 * NH + h0 + 1] = p1[1];
                    }
                    if (r2 < Mrows) {
                        eo[(size_t)r2 * NH + h0]     = p2[0];
                        eo[(size_t)r2 * NH + h0 + 1] = p2[1];
                    }
                }
            }
        }
    } else {
        if (tid < 128) redbuf[tid] = 0.f;
        __syncthreads();
#pragma unroll
        for (int mt = 0; mt < 4; mt++) {
            float p1 = 0.f, p2 = 0.f;
#pragma unroll
            for (int nt = 0; nt < 4; nt++) {
                int c = warp_n * 32 + nt * 8 + j * 2;
                float b0 = bias[c], b1 = bias[c + 1];
                float w0 = w2[c], w1 = w2[c + 1];
                p1 += tanhf(cfr[mt][nt][0] + b0) * w0 + tanhf(cfr[mt][nt][1] + b1) * w1;
                p2 += tanhf(cfr[mt][nt][2] + b0) * w0 + tanhf(cfr[mt][nt][3] + b1) * w1;
            }
            p1 += __shfl_xor_sync(0xffffffffu, p1, 1);
            p1 += __shfl_xor_sync(0xffffffffu, p1, 2);
            p2 += __shfl_xor_sync(0xffffffffu, p2, 1);
            p2 += __shfl_xor_sync(0xffffffffu, p2, 2);
            if (j == 0) {
                atomicAdd(&redbuf[warp_m * 64 + mt * 16 + g], p1);
                atomicAdd(&redbuf[warp_m * 64 + mt * 16 + g + 8], p2);
            }
        }
        __syncthreads();
        if (tid < 128) {
            int r = rowBase + tid;
            if (r < Mrows) wout[r] = redbuf[tid];
        }
    }
}

// ---------------- er[m][n][h] = h_[n,:] . Vdst[m][h][:] (one warp per node) -
__global__ void er_kernel(const float* __restrict__ hfeat, const float* __restrict__ vd,
                          float* __restrict__ er)
{
    __shared__ float sV[MM * NH * HID];
    for (int i = threadIdx.x; i < MM * NH * HID; i += blockDim.x) sV[i] = vd[i];
    __syncthreads();
    int warp = (blockIdx.x * blockDim.x + threadIdx.x) >> 5;
    int lane = threadIdx.x & 31;
    if (warp >= NN) return;
    float4 hv = *reinterpret_cast<const float4*>(hfeat + (size_t)warp * HID + lane * 4);
#pragma unroll
    for (int m = 0; m < MM; m++) {
#pragma unroll
        for (int hh = 0; hh < NH; hh++) {
            float4 vv = *reinterpret_cast<const float4*>(&sV[(m * NH + hh) * HID + lane * 4]);
            float p = hv.x * vv.x + hv.y * vv.y + hv.z * vv.z + hv.w * vv.w;
            p += __shfl_xor_sync(0xffffffffu, p, 16);
            p += __shfl_xor_sync(0xffffffffu, p, 8);
            p += __shfl_xor_sync(0xffffffffu, p, 4);
            p += __shfl_xor_sync(0xffffffffu, p, 2);
            p += __shfl_xor_sync(0xffffffffu, p, 1);
            if (lane == 0) er[((size_t)m * NN + warp) * NH + hh] = p;
        }
    }
}

// ---------------- CSR build: count / scan / fill ----------------------------
__global__ void count_kernel(const int* __restrict__ dst, int* __restrict__ cnt)
{
    int t = blockIdx.x * blockDim.x + threadIdx.x;
    if (t >= MM * EE) return;
    int m = t / EE;
    atomicAdd(&cnt[m * NN + dst[t]], 1);
}

#define SCAN_T 1024
#define SCAN_CH ((SEGS + SCAN_T - 1) / SCAN_T)
__global__ void __launch_bounds__(SCAN_T) scan_kernel(const int* __restrict__ cnt,
                                                      int* __restrict__ off,
                                                      int* __restrict__ pos)
{
    __shared__ int sm[SCAN_T];
    int tid = threadIdx.x;
    int base = tid * SCAN_CH;
    int s = 0;
    for (int i = 0; i < SCAN_CH; i++) {
        int idx = base + i;
        if (idx < SEGS) s += cnt[idx];
    }
    sm[tid] = s;
    __syncthreads();
    for (int d = 1; d < SCAN_T; d <<= 1) {
        int v = (tid >= d) ? sm[tid - d] : 0;
        __syncthreads();
        sm[tid] += v;
        __syncthreads();
    }
    int run = sm[tid] - s;
    for (int i = 0; i < SCAN_CH; i++) {
        int idx = base + i;
        if (idx < SEGS) {
            off[idx] = run;
            pos[idx] = run;
            run += cnt[idx];
        }
    }
}

__global__ void fill_kernel(const int* __restrict__ src, const int* __restrict__ dst,
                            int* __restrict__ pos, int* __restrict__ ssrc)
{
    int t = blockIdx.x * blockDim.x + threadIdx.x;
    if (t >= MM * EE) return;
    int m = t / EE;
    int p = atomicAdd(&pos[m * NN + dst[t]], 1);
    ssrc[p] = src[t];
}

// ---------------- gather: single pass, 2-way unrolled for MLP ---------------
// out = (sum_i e_i * fs_i) / (sum_i e_i)
__global__ void gather_kernel(const int* __restrict__ ssrc,
                              const int* __restrict__ off, const int* __restrict__ cnt,
                              const float* __restrict__ el, const float* __restrict__ er,
                              const float* __restrict__ fs, float* __restrict__ z)
{
    int gw = (blockIdx.x * blockDim.x + threadIdx.x) >> 5;
    int lane = threadIdx.x & 31;
    if (gw >= SEGS) return;
    int m = gw / NN;
    int n = gw - m * NN;
    int beg = off[gw];
    int num = cnt[gw];
    const float* elm = el + (size_t)m * NN * NH;
    const float* fsm = fs + (size_t)m * NN * HID;

    int h4 = lane >> 2;
    float er4 = er[(size_t)gw * NH + h4];

    float ssum0 = 0.f, ssum1 = 0.f;
    float4 acc0 = make_float4(0.f, 0.f, 0.f, 0.f);
    float4 acc1 = make_float4(0.f, 0.f, 0.f, 0.f);
    int it = 0;
    for (; it + 1 < num; it += 2) {
        int s0 = ssrc[beg + it];
        int s1 = ssrc[beg + it + 1];
        float v0 = elm[s0 * NH + h4] + er4;
        float v1 = elm[s1 * NH + h4] + er4;
        float4 f0 = *reinterpret_cast<const float4*>(fsm + (size_t)s0 * HID + lane * 4);
        float4 f1 = *reinterpret_cast<const float4*>(fsm + (size_t)s1 * HID + lane * 4);
        v0 = v0 > 0.f ? v0 : 0.2f * v0;
        v1 = v1 > 0.f ? v1 : 0.2f * v1;
        float e0 = __expf(v0);
        float e1 = __expf(v1);
        ssum0 += e0; ssum1 += e1;
        acc0.x += f0.x * e0; acc0.y += f0.y * e0; acc0.z += f0.z * e0; acc0.w += f0.w * e0;
        acc1.x += f1.x * e1; acc1.y += f1.y * e1; acc1.z += f1.z * e1; acc1.w += f1.w * e1;
    }
    if (it < num) {
        int s0 = ssrc[beg + it];
        float v0 = elm[s0 * NH + h4] + er4;
        float4 f0 = *reinterpret_cast<const float4*>(fsm + (size_t)s0 * HID + lane * 4);
        v0 = v0 > 0.f ? v0 : 0.2f * v0;
        float e0 = __expf(v0);
        ssum0 += e0;
        acc0.x += f0.x * e0; acc0.y += f0.y * e0; acc0.z += f0.z * e0; acc0.w += f0.w * e0;
    }
    float inv = 1.f / fmaxf(ssum0 + ssum1, 1e-9f);
    float4 o;
    o.x = (acc0.x + acc1.x) * inv;
    o.y = (acc0.y + acc1.y) * inv;
    o.z = (acc0.z + acc1.z) * inv;
    o.w = (acc0.w + acc1.w) * inv;
    *reinterpret_cast<float4*>(z + ((size_t)n * MM + m) * HID + lane * 4) = o;
}

// ---------------- final: beta softmax over w, elu(z) fuse, output GEMV ------
__global__ void final_kernel(const float* __restrict__ w, const float* __restrict__ z,
                             const float* __restrict__ Wout, const float* __restrict__ bout,
                             float* __restrict__ out)
{
    __shared__ float sW[HID * OUTD];
    for (int i = threadIdx.x; i < HID * OUTD; i += blockDim.x) sW[i] = Wout[i];
    __syncthreads();
    int warp = (blockIdx.x * blockDim.x + threadIdx.x) >> 5;
    int lane = threadIdx.x & 31;
    if (warp >= NN) return;
    float w0 = w[warp * 3 + 0], w1 = w[warp * 3 + 1], w2v = w[warp * 3 + 2];
    float mx = fmaxf(w0, fmaxf(w1, w2v));
    float e0 = __expf(w0 - mx), e1 = __expf(w1 - mx), e2 = __expf(w2v - mx);
    float inv = 1.f / (e0 + e1 + e2);
    float b0 = e0 * inv, b1 = e1 * inv, b2 = e2 * inv;
    const float* zr = z + (size_t)warp * (MM * HID);
    float4 z0 = *reinterpret_cast<const float4*>(zr + lane * 4);
    float4 z1 = *reinterpret_cast<const float4*>(zr + HID + lane * 4);
    float4 z2 = *reinterpret_cast<const float4*>(zr + 2 * HID + lane * 4);
    float f[4];
    f[0] = b0 * elu1(z0.x) + b1 * elu1(z1.x) + b2 * elu1(z2.x);
    f[1] = b0 * elu1(z0.y) + b1 * elu1(z1.y) + b2 * elu1(z2.y);
    f[2] = b0 * elu1(z0.z) + b1 * elu1(z1.z) + b2 * elu1(z2.z);
    f[3] = b0 * elu1(z0.w) + b1 * elu1(z1.w) + b2 * elu1(z2.w);
    float po[OUTD];
#pragma unroll
    for (int o = 0; o < OUTD; o++) {
        po[o] = 0.f;
#pragma unroll
        for (int j = 0; j < 4; j++)
            po[o] += f[j] * sW[(lane * 4 + j) * OUTD + o];
    }
#pragma unroll
    for (int off = 16; off; off >>= 1)
#pragma unroll
        for (int o = 0; o < OUTD; o++)
            po[o] += __shfl_down_sync(0xffffffffu, po[o], off);
    if (lane == 0)
#pragma unroll
        for (int o = 0; o < OUTD; o++)
            out[(size_t)warp * OUTD + o] = po[o] + bout[o];
}

// ---------------- launch ----------------------------------------------------
extern "C" void kernel_launch(void* const* d_in, const int* in_sizes, int n_in,
                              void* d_out, int out_size)
{
    const float* features = (const float*)d_in[0];
    const float* W_fc     = (const float*)d_in[1];
    const float* b_fc     = (const float*)d_in[2];
    const float* W_src    = (const float*)d_in[3];
    const float* W_dst    = (const float*)d_in[4];
    const float* attn_l   = (const float*)d_in[5];
    const float* attn_r   = (const float*)d_in[6];
    const float* W_sem1   = (const float*)d_in[7];
    const float* b_sem1   = (const float*)d_in[8];
    const float* w_sem2   = (const float*)d_in[9];
    const float* W_out    = (const float*)d_in[10];
    const float* b_out    = (const float*)d_in[11];
    const int*   src_idx  = (const int*)d_in[12];
    const int*   dst_idx  = (const int*)d_in[13];
    float* out = (float*)d_out;

    float *h, *fs, *el, *er, *vd, *z, *w;
    int *cnt, *off, *pos, *ssrc;
    __nv_bfloat16 *bfc, *bpr, *bsm;
    cudaGetSymbolAddress((void**)&h,   d_h);
    cudaGetSymbolAddress((void**)&fs,  d_fs);
    cudaGetSymbolAddress((void**)&el,  d_el);
    cudaGetSymbolAddress((void**)&er,  d_er);
    cudaGetSymbolAddress((void**)&vd,  d_vd);
    cudaGetSymbolAddress((void**)&z,   d_z);
    cudaGetSymbolAddress((void**)&w,   d_w);
    cudaGetSymbolAddress((void**)&cnt, d_cnt);
    cudaGetSymbolAddress((void**)&off, d_off);
    cudaGetSymbolAddress((void**)&pos, d_pos);
    cudaGetSymbolAddress((void**)&ssrc,d_ssrc);
    cudaGetSymbolAddress((void**)&bfc, d_Bfc);
    cudaGetSymbolAddress((void**)&bpr, d_Bpr);
    cudaGetSymbolAddress((void**)&bsm, d_Bsm);

    cudaMemsetAsync(cnt, 0, SEGS * sizeof(int));

    // all weight prep + vdst in one launch
    prep_all<<<dim3((128 * F_IN + 255) / 256, 6), 256>>>(W_fc, W_src, W_sem1,
                                                         W_dst, attn_r);

    // CSR build
    count_kernel<<<(MM * EE + 255) / 256, 256>>>(dst_idx, cnt);
    scan_kernel<<<1, SCAN_T>>>(cnt, off, pos);
    fill_kernel<<<(MM * EE + 255) / 256, 256>>>(src_idx, dst_idx, pos, ssrc);

    const int MT = (NN + 127) / 128;

    // h = features @ W_fc + b_fc
    mgemm<<<dim3(MT, 1), 256>>>(features, bfc, b_fc, h,
                                nullptr, nullptr, nullptr, nullptr,
                                NN, F_IN, 0);

    // fs[m] = h @ W_src[m], fused el; er via factored Vdst
    mgemm<<<dim3(MT, MM), 256>>>(h, bpr, nullptr, fs,
                                 attn_l, el, nullptr, nullptr,
                                 NN, HID, 1);
    er_kernel<<<(NN + 7) / 8, 256>>>(h, vd, er);

    // edge softmax + aggregation, single pass, atomic-free
    gather_kernel<<<(SEGS + 7) / 8, 256>>>(ssrc, off, cnt, el, er, fs, z);

    // semantic: w = tanh(elu(z) @ W_sem1 + b_sem1) . w_sem2
    mgemm<<<dim3((NN * MM + 127) / 128, 1), 256>>>(z, bsm, b_sem1, nullptr,
                                 nullptr, nullptr, w_sem2, w,
                                 NN * MM, HID, 2);

    final_kernel<<<(NN + 7) / 8, 256>>>(w, z, W_out, b_out, out);
}

// round 14
// speedup vs baseline: 1.2865x; 1.2865x over previous
#include <cuda_runtime.h>
#include <cuda_bf16.h>
#include <cstdint>

#define NN   50000
#define F_IN 256
#define HID  128
#define NH   8
#define EE   800000
#define MM   3
#define OUTD 8
#define SEGS (MM * NN)
#define CK   32   // K-chunk
#define ASTR 40   // padded smem row stride (halves)

// ---------------- scratch (device globals; no allocation) ----------------
__device__ float d_h [NN * HID];
__device__ float d_fs[(size_t)MM * NN * HID];
__device__ float d_el[(size_t)MM * NN * NH];
__device__ float d_er[(size_t)MM * NN * NH];
__device__ float d_vd[MM * NH * HID];
__device__ float d_z [(size_t)NN * MM * HID];
__device__ float d_w [NN * MM];
__device__ int   d_cnt [SEGS];
__device__ int   d_off [SEGS];
__device__ int   d_pos [SEGS];
__device__ int   d_ssrc[MM * EE];
// B' transposed weights, [128][2K]: [n][0..K)=hi, [n][K..2K)=lo
__device__ __nv_bfloat16 d_Bfc[128 * 2 * F_IN];
__device__ __nv_bfloat16 d_Bpr[MM * 128 * 2 * HID];
__device__ __nv_bfloat16 d_Bsm[128 * 2 * HID];

__device__ __forceinline__ float elu1(float v)
{
    return v > 0.f ? v : (__expf(v) - 1.f);
}

__device__ __forceinline__ uint32_t smem_u32(const void* p) {
    uint32_t a;
    asm("{ .reg .u64 t; cvta.to.shared.u64 t, %1; cvt.u32.u64 %0, t; }"
        : "=r"(a) : "l"(p));
    return a;
}

// ---------------- unified prep: all weight splits + Vdst in ONE launch ------
// blockIdx.y: 0 = W_fc->d_Bfc (K=256); 1..3 = W_src[m]->d_Bpr (K=128);
//             4 = W_sem1->d_Bsm (K=128); 5 = vdst
__global__ void prep_all(const float* __restrict__ W_fc,
                         const float* __restrict__ W_src,
                         const float* __restrict__ W_sem1,
                         const float* __restrict__ W_dst,
                         const float* __restrict__ ar)
{
    int y = blockIdx.y;
    int t = blockIdx.x * blockDim.x + threadIdx.x;
    if (y == 5) {
        if (t >= MM * NH * HID) return;
        int m = t / (NH * HID);
        int r = t - m * (NH * HID);
        int h = r / HID;
        int k = r - h * HID;
        const float* W = W_dst + ((size_t)m * HID + k) * HID + h * 16;
        const float* a = ar + (m * NH + h) * 16;
        float s = 0.f;
#pragma unroll
        for (int d = 0; d < 16; d++) s += W[d] * a[d];
        d_vd[(m * NH + h) * HID + k] = s;
        return;
    }
    const float* W;
    __nv_bfloat16* Bp;
    int K;
    if (y == 0)      { W = W_fc;   Bp = d_Bfc; K = F_IN; }
    else if (y <= 3) { int m = y - 1; W = W_src + (size_t)m * HID * HID;
                       Bp = d_Bpr + (size_t)m * 128 * 2 * HID; K = HID; }
    else             { W = W_sem1; Bp = d_Bsm; K = HID; }
    if (t >= 128 * K) return;
    int k = t >> 7;
    int n = t & 127;
    float v = W[(size_t)k * 128 + n];
    __nv_bfloat16 h = __float2bfloat16(v);
    __nv_bfloat16 l = __float2bfloat16(v - __bfloat162float(h));
    size_t base = (size_t)n * 2 * K;
    Bp[base + k]     = h;
    Bp[base + K + k] = l;
}

// ---------------- tensor-core GEMM via mma.sync, bf16 hi/lo split -----------
// D = Ah@Bh + Ah@Bl + Al@Bh  (fp32 accum); tile 128x128, 8 warps (2x4)
// mode 0: C = A@W + bias     mode 1 (grid.y=m): C = A@W ; el head-dots fused
// mode 2: A'=elu(A); wout = tanh(A'@W + bias) . w2  (no C store)
__global__ void __launch_bounds__(256) mgemm(
    const float* __restrict__ A, const __nv_bfloat16* __restrict__ Bp,
    const float* __restrict__ bias, float* __restrict__ Cb,
    const float* __restrict__ att, float* __restrict__ elb,
    const float* __restrict__ w2, float* __restrict__ wout,
    int Mrows, int K, int mode)
{
    __shared__ __nv_bfloat16 Ah[128 * ASTR];
    __shared__ __nv_bfloat16 Al[128 * ASTR];
    __shared__ __nv_bfloat16 Bh[128 * ASTR];
    __shared__ __nv_bfloat16 Bl[128 * ASTR];
    __shared__ float redbuf[128];

    const int tid = threadIdx.x;
    const int lane = tid & 31;
    const int wid = tid >> 5;
    const int warp_m = wid >> 2;      // 0..1 -> rows warp_m*64
    const int warp_n = wid & 3;       // 0..3 -> cols warp_n*32
    const int rowBase = blockIdx.x * 128;

    const __nv_bfloat16* B = Bp;
    float* C = Cb; const float* av = att; float* eo = elb;
    if (mode == 1) {
        int m = blockIdx.y;
        B  += (size_t)m * 128 * 2 * K;
        C  += (size_t)m * NN * HID;
        av += (size_t)m * HID;
        eo += (size_t)m * NN * NH;
    }

    float cfr[4][4][4];
#pragma unroll
    for (int mt = 0; mt < 4; mt++)
#pragma unroll
        for (int nt = 0; nt < 4; nt++)
#pragma unroll
            for (int q = 0; q < 4; q++) cfr[mt][nt][q] = 0.f;

    // loader mapping: row = tid>>1, 16-wide half-chunk = (tid&1)*16
    const int lrow = tid >> 1;
    const int lcol = (tid & 1) * 16;
    const bool aok = (rowBase + lrow) < Mrows;
    const float* Arow = A + (size_t)(rowBase + lrow) * K;
    const __nv_bfloat16* Bh_row = B + (size_t)lrow * 2 * K;
    const __nv_bfloat16* Bl_row = Bh_row + K;

    const uint32_t ahb = smem_u32(Ah);
    const uint32_t alb = smem_u32(Al);
    const uint32_t bhb = smem_u32(Bh);
    const uint32_t blb = smem_u32(Bl);

    for (int kc = 0; kc < K; kc += CK) {
        // ---- load A chunk fp32 -> hi/lo bf16 ----
        {
            uint32_t* dh = reinterpret_cast<uint32_t*>(&Ah[lrow * ASTR + lcol]);
            uint32_t* dl = reinterpret_cast<uint32_t*>(&Al[lrow * ASTR + lcol]);
#pragma unroll
            for (int q = 0; q < 4; q++) {
                float4 v = aok ? *reinterpret_cast<const float4*>(Arow + kc + lcol + q * 4)
                               : make_float4(0.f, 0.f, 0.f, 0.f);
                if (mode == 2) { v.x = elu1(v.x); v.y = elu1(v.y); v.z = elu1(v.z); v.w = elu1(v.w); }
                __nv_bfloat16 h0 = __float2bfloat16(v.x);
                __nv_bfloat16 h1 = __float2bfloat16(v.y);
                __nv_bfloat16 h2 = __float2bfloat16(v.z);
                __nv_bfloat16 h3 = __float2bfloat16(v.w);
                __nv_bfloat16 l0 = __float2bfloat16(v.x - __bfloat162float(h0));
                __nv_bfloat16 l1 = __float2bfloat16(v.y - __bfloat162float(h1));
                __nv_bfloat16 l2 = __float2bfloat16(v.z - __bfloat162float(h2));
                __nv_bfloat16 l3 = __float2bfloat16(v.w - __bfloat162float(h3));
                __nv_bfloat162 hp0 = __halves2bfloat162(h0, h1);
                __nv_bfloat162 hp1 = __halves2bfloat162(h2, h3);
                __nv_bfloat162 lp0 = __halves2bfloat162(l0, l1);
                __nv_bfloat162 lp1 = __halves2bfloat162(l2, l3);
                dh[q * 2]     = *reinterpret_cast<uint32_t*>(&hp0);
                dh[q * 2 + 1] = *reinterpret_cast<uint32_t*>(&hp1);
                dl[q * 2]     = *reinterpret_cast<uint32_t*>(&lp0);
                dl[q * 2 + 1] = *reinterpret_cast<uint32_t*>(&lp1);
            }
        }
        // ---- load B hi/lo chunks (pre-split, straight copy) ----
        {
            const uint4* gh = reinterpret_cast<const uint4*>(Bh_row + kc + lcol);
            const uint4* gl = reinterpret_cast<const uint4*>(Bl_row + kc + lcol);
            uint4* dh = reinterpret_cast<uint4*>(&Bh[lrow * ASTR + lcol]);
            uint4* dl = reinterpret_cast<uint4*>(&Bl[lrow * ASTR + lcol]);
            dh[0] = gh[0]; dh[1] = gh[1];
            dl[0] = gl[0]; dl[1] = gl[1];
        }
        __syncthreads();

        // ---- 2 k-steps of 16 ----
#pragma unroll
        for (int ks = 0; ks < 2; ks++) {
            int k0 = ks * 16;
            int ra = warp_m * 64 + (lane & 15);
            int ka = k0 + (lane >> 4) * 8;
            int nb = warp_n * 32 + (lane & 7);
            int kb = k0 + ((lane >> 3) & 1) * 8;

            uint32_t ah[4][4], bh[4][2], bl[4][2];
#pragma unroll
            for (int mt = 0; mt < 4; mt++) {
                uint32_t addr = ahb + (uint32_t)((ra + mt * 16) * ASTR + ka) * 2u;
                asm volatile("ldmatrix.sync.aligned.m8n8.x4.shared.b16 {%0,%1,%2,%3}, [%4];"
                             : "=r"(ah[mt][0]), "=r"(ah[mt][1]), "=r"(ah[mt][2]), "=r"(ah[mt][3])
                             : "r"(addr));
            }
#pragma unroll
            for (int nt = 0; nt < 4; nt++) {
                uint32_t addr = bhb + (uint32_t)((nb + nt * 8) * ASTR + kb) * 2u;
                asm volatile("ldmatrix.sync.aligned.m8n8.x2.shared.b16 {%0,%1}, [%2];"
                             : "=r"(bh[nt][0]), "=r"(bh[nt][1]) : "r"(addr));
                uint32_t addr2 = blb + (uint32_t)((nb + nt * 8) * ASTR + kb) * 2u;
                asm volatile("ldmatrix.sync.aligned.m8n8.x2.shared.b16 {%0,%1}, [%2];"
                             : "=r"(bl[nt][0]), "=r"(bl[nt][1]) : "r"(addr2));
            }
#pragma unroll
            for (int mt = 0; mt < 4; mt++)
#pragma unroll
                for (int nt = 0; nt < 4; nt++) {
                    asm volatile(
                        "mma.sync.aligned.m16n8k16.row.col.f32.bf16.bf16.f32 "
                        "{%0,%1,%2,%3}, {%4,%5,%6,%7}, {%8,%9}, {%0,%1,%2,%3};"
                        : "+f"(cfr[mt][nt][0]), "+f"(cfr[mt][nt][1]),
                          "+f"(cfr[mt][nt][2]), "+f"(cfr[mt][nt][3])
                        : "r"(ah[mt][0]), "r"(ah[mt][1]), "r"(ah[mt][2]), "r"(ah[mt][3]),
                          "r"(bh[nt][0]), "r"(bh[nt][1]));
                    asm volatile(
                        "mma.sync.aligned.m16n8k16.row.col.f32.bf16.bf16.f32 "
                        "{%0,%1,%2,%3}, {%4,%5,%6,%7}, {%8,%9}, {%0,%1,%2,%3};"
                        : "+f"(cfr[mt][nt][0]), "+f"(cfr[mt][nt][1]),
                          "+f"(cfr[mt][nt][2]), "+f"(cfr[mt][nt][3])
                        : "r"(ah[mt][0]), "r"(ah[mt][1]), "r"(ah[mt][2]), "r"(ah[mt][3]),
                          "r"(bl[nt][0]), "r"(bl[nt][1]));
                }
            // A_lo frags after hi frags retire (register pressure)
            uint32_t al4[4][4];
#pragma unroll
            for (int mt = 0; mt < 4; mt++) {
                uint32_t addr = alb + (uint32_t)((ra + mt * 16) * ASTR + ka) * 2u;
                asm volatile("ldmatrix.sync.aligned.m8n8.x4.shared.b16 {%0,%1,%2,%3}, [%4];"
                             : "=r"(al4[mt][0]), "=r"(al4[mt][1]), "=r"(al4[mt][2]), "=r"(al4[mt][3])
                             : "r"(addr));
            }
#pragma unroll
            for (int mt = 0; mt < 4; mt++)
#pragma unroll
                for (int nt = 0; nt < 4; nt++) {
                    asm volatile(
                        "mma.sync.aligned.m16n8k16.row.col.f32.bf16.bf16.f32 "
                        "{%0,%1,%2,%3}, {%4,%5,%6,%7}, {%8,%9}, {%0,%1,%2,%3};"
                        : "+f"(cfr[mt][nt][0]), "+f"(cfr[mt][nt][1]),
                          "+f"(cfr[mt][nt][2]), "+f"(cfr[mt][nt][3])
                        : "r"(al4[mt][0]), "r"(al4[mt][1]), "r"(al4[mt][2]), "r"(al4[mt][3]),
                          "r"(bh[nt][0]), "r"(bh[nt][1]));
                }
        }
        __syncthreads();
    }

    // ---- epilogues ----
    const int g = lane >> 2, j = lane & 3;

    if (mode == 0 || mode == 1) {
#pragma unroll
        for (int mt = 0; mt < 4; mt++) {
            int r1 = rowBase + warp_m * 64 + mt * 16 + g;
            int r2 = r1 + 8;
#pragma unroll
            for (int nt = 0; nt < 4; nt++) {
                int c = warp_n * 32 + nt * 8 + j * 2;
                float b0 = 0.f, b1 = 0.f;
                if (mode == 0) { b0 = bias[c]; b1 = bias[c + 1]; }
                if (r1 < Mrows)
                    *reinterpret_cast<float2*>(C + (size_t)r1 * HID + c) =
                        make_float2(cfr[mt][nt][0] + b0, cfr[mt][nt][1] + b1);
                if (r2 < Mrows)
                    *reinterpret_cast<float2*>(C + (size_t)r2 * HID + c) =
                        make_float2(cfr[mt][nt][2] + b0, cfr[mt][nt][3] + b1);
            }
            if (mode == 1) {
                float p1[2] = {0.f, 0.f}, p2[2] = {0.f, 0.f};
#pragma unroll
                for (int nt = 0; nt < 4; nt++) {
                    int hl = nt >> 1;
                    int c = warp_n * 32 + nt * 8 + j * 2;
                    float a0 = av[c], a1 = av[c + 1];
                    p1[hl] += cfr[mt][nt][0] * a0 + cfr[mt][nt][1] * a1;
                    p2[hl] += cfr[mt][nt][2] * a0 + cfr[mt][nt][3] * a1;
                }
#pragma unroll
                for (int hl = 0; hl < 2; hl++) {
                    p1[hl] += __shfl_xor_sync(0xffffffffu, p1[hl], 1);
                    p1[hl] += __shfl_xor_sync(0xffffffffu, p1[hl], 2);
                    p2[hl] += __shfl_xor_sync(0xffffffffu, p2[hl], 1);
                    p2[hl] += __shfl_xor_sync(0xffffffffu, p2[hl], 2);
                }
                if (j == 0) {
                    int h0 = warp_n * 2;
                    if (r1 < Mrows) {
                        eo[(size_t)r1 * NH + h0]     = p1[0];
                        eo[(size_t)r1 * NH + h0 + 1] = p1[1];
                    }
                    if (r2 < Mrows) {
                        eo[(size_t)r2 * NH + h0]     = p2[0];
                        eo[(size_t)r2 * NH + h0 + 1] = p2[1];
                    }
                }
            }
        }
    } else {
        if (tid < 128) redbuf[tid] = 0.f;
        __syncthreads();
#pragma unroll
        for (int mt = 0; mt < 4; mt++) {
            float p1 = 0.f, p2 = 0.f;
#pragma unroll
            for (int nt = 0; nt < 4; nt++) {
                int c = warp_n * 32 + nt * 8 + j * 2;
                float b0 = bias[c], b1 = bias[c + 1];
                float w0 = w2[c], w1 = w2[c + 1];
                p1 += tanhf(cfr[mt][nt][0] + b0) * w0 + tanhf(cfr[mt][nt][1] + b1) * w1;
                p2 += tanhf(cfr[mt][nt][2] + b0) * w0 + tanhf(cfr[mt][nt][3] + b1) * w1;
            }
            p1 += __shfl_xor_sync(0xffffffffu, p1, 1);
            p1 += __shfl_xor_sync(0xffffffffu, p1, 2);
            p2 += __shfl_xor_sync(0xffffffffu, p2, 1);
            p2 += __shfl_xor_sync(0xffffffffu, p2, 2);
            if (j == 0) {
                atomicAdd(&redbuf[warp_m * 64 + mt * 16 + g], p1);
                atomicAdd(&redbuf[warp_m * 64 + mt * 16 + g + 8], p2);
            }
        }
        __syncthreads();
        if (tid < 128) {
            int r = rowBase + tid;
            if (r < Mrows) wout[r] = redbuf[tid];
        }
    }
}

// ---------------- er[m][n][h] = h_[n,:] . Vdst[m][h][:] (one warp per node) -
__global__ void er_kernel(const float* __restrict__ hfeat, const float* __restrict__ vd,
                          float* __restrict__ er)
{
    __shared__ float sV[MM * NH * HID];
    for (int i = threadIdx.x; i < MM * NH * HID; i += blockDim.x) sV[i] = vd[i];
    __syncthreads();
    int warp = (blockIdx.x * blockDim.x + threadIdx.x) >> 5;
    int lane = threadIdx.x & 31;
    if (warp >= NN) return;
    float4 hv = *reinterpret_cast<const float4*>(hfeat + (size_t)warp * HID + lane * 4);
#pragma unroll
    for (int m = 0; m < MM; m++) {
#pragma unroll
        for (int hh = 0; hh < NH; hh++) {
            float4 vv = *reinterpret_cast<const float4*>(&sV[(m * NH + hh) * HID + lane * 4]);
            float p = hv.x * vv.x + hv.y * vv.y + hv.z * vv.z + hv.w * vv.w;
            p += __shfl_xor_sync(0xffffffffu, p, 16);
            p += __shfl_xor_sync(0xffffffffu, p, 8);
            p += __shfl_xor_sync(0xffffffffu, p, 4);
            p += __shfl_xor_sync(0xffffffffu, p, 2);
            p += __shfl_xor_sync(0xffffffffu, p, 1);
            if (lane == 0) er[((size_t)m * NN + warp) * NH + hh] = p;
        }
    }
}

// ---------------- CSR build: count / scan / fill ----------------------------
__global__ void count_kernel(const int* __restrict__ dst, int* __restrict__ cnt)
{
    int t = blockIdx.x * blockDim.x + threadIdx.x;
    if (t >= MM * EE) return;
    int m = t / EE;
    atomicAdd(&cnt[m * NN + dst[t]], 1);
}

#define SCAN_T 1024
#define SCAN_CH ((SEGS + SCAN_T - 1) / SCAN_T)
__global__ void __launch_bounds__(SCAN_T) scan_kernel(const int* __restrict__ cnt,
                                                      int* __restrict__ off,
                                                      int* __restrict__ pos)
{
    __shared__ int sm[SCAN_T];
    int tid = threadIdx.x;
    int base = tid * SCAN_CH;
    int s = 0;
    for (int i = 0; i < SCAN_CH; i++) {
        int idx = base + i;
        if (idx < SEGS) s += cnt[idx];
    }
    sm[tid] = s;
    __syncthreads();
    for (int d = 1; d < SCAN_T; d <<= 1) {
        int v = (tid >= d) ? sm[tid - d] : 0;
        __syncthreads();
        sm[tid] += v;
        __syncthreads();
    }
    int run = sm[tid] - s;
    for (int i = 0; i < SCAN_CH; i++) {
        int idx = base + i;
        if (idx < SEGS) {
            off[idx] = run;
            pos[idx] = run;
            run += cnt[idx];
        }
    }
}

__global__ void fill_kernel(const int* __restrict__ src, const int* __restrict__ dst,
                            int* __restrict__ pos, int* __restrict__ ssrc)
{
    int t = blockIdx.x * blockDim.x + threadIdx.x;
    if (t >= MM * EE) return;
    int m = t / EE;
    int p = atomicAdd(&pos[m * NN + dst[t]], 1);
    ssrc[p] = src[t];
}

// ---------------- gather: single pass, 2-way unrolled -----------------------
// out = (sum_i e_i * fs_i) / (sum_i e_i)
__global__ void gather_kernel(const int* __restrict__ ssrc,
                              const int* __restrict__ off, const int* __restrict__ cnt,
                              const float* __restrict__ el, const float* __restrict__ er,
                              const float* __restrict__ fs, float* __restrict__ z)
{
    int gw = (blockIdx.x * blockDim.x + threadIdx.x) >> 5;
    int lane = threadIdx.x & 31;
    if (gw >= SEGS) return;
    int m = gw / NN;
    int n = gw - m * NN;
    int beg = off[gw];
    int num = cnt[gw];
    const float* elm = el + (size_t)m * NN * NH;
    const float* fsm = fs + (size_t)m * NN * HID;

    int h4 = lane >> 2;
    float er4 = er[(size_t)gw * NH + h4];

    float ssum0 = 0.f, ssum1 = 0.f;
    float4 acc0 = make_float4(0.f, 0.f, 0.f, 0.f);
    float4 acc1 = make_float4(0.f, 0.f, 0.f, 0.f);
    int it = 0;
    for (; it + 1 < num; it += 2) {
        int s0 = ssrc[beg + it];
        int s1 = ssrc[beg + it + 1];
        float v0 = elm[s0 * NH + h4] + er4;
        float v1 = elm[s1 * NH + h4] + er4;
        float4 f0 = *reinterpret_cast<const float4*>(fsm + (size_t)s0 * HID + lane * 4);
        float4 f1 = *reinterpret_cast<const float4*>(fsm + (size_t)s1 * HID + lane * 4);
        v0 = v0 > 0.f ? v0 : 0.2f * v0;
        v1 = v1 > 0.f ? v1 : 0.2f * v1;
        float e0 = __expf(v0);
        float e1 = __expf(v1);
        ssum0 += e0; ssum1 += e1;
        acc0.x += f0.x * e0; acc0.y += f0.y * e0; acc0.z += f0.z * e0; acc0.w += f0.w * e0;
        acc1.x += f1.x * e1; acc1.y += f1.y * e1; acc1.z += f1.z * e1; acc1.w += f1.w * e1;
    }
    if (it < num) {
        int s0 = ssrc[beg + it];
        float v0 = elm[s0 * NH + h4] + er4;
        float4 f0 = *reinterpret_cast<const float4*>(fsm + (size_t)s0 * HID + lane * 4);
        v0 = v0 > 0.f ? v0 : 0.2f * v0;
        float e0 = __expf(v0);
        ssum0 += e0;
        acc0.x += f0.x * e0; acc0.y += f0.y * e0; acc0.z += f0.z * e0; acc0.w += f0.w * e0;
    }
    float inv = 1.f / fmaxf(ssum0 + ssum1, 1e-9f);
    float4 o;
    o.x = (acc0.x + acc1.x) * inv;
    o.y = (acc0.y + acc1.y) * inv;
    o.z = (acc0.z + acc1.z) * inv;
    o.w = (acc0.w + acc1.w) * inv;
    *reinterpret_cast<float4*>(z + ((size_t)n * MM + m) * HID + lane * 4) = o;
}

// ---------------- final: beta softmax over w, elu(z) fuse, output GEMV ------
__global__ void final_kernel(const float* __restrict__ w, const float* __restrict__ z,
                             const float* __restrict__ Wout, const float* __restrict__ bout,
                             float* __restrict__ out)
{
    __shared__ float sW[HID * OUTD];
    for (int i = threadIdx.x; i < HID * OUTD; i += blockDim.x) sW[i] = Wout[i];
    __syncthreads();
    int warp = (blockIdx.x * blockDim.x + threadIdx.x) >> 5;
    int lane = threadIdx.x & 31;
    if (warp >= NN) return;
    float w0 = w[warp * 3 + 0], w1 = w[warp * 3 + 1], w2v = w[warp * 3 + 2];
    float mx = fmaxf(w0, fmaxf(w1, w2v));
    float e0 = __expf(w0 - mx), e1 = __expf(w1 - mx), e2 = __expf(w2v - mx);
    float inv = 1.f / (e0 + e1 + e2);
    float b0 = e0 * inv, b1 = e1 * inv, b2 = e2 * inv;
    const float* zr = z + (size_t)warp * (MM * HID);
    float4 z0 = *reinterpret_cast<const float4*>(zr + lane * 4);
    float4 z1 = *reinterpret_cast<const float4*>(zr + HID + lane * 4);
    float4 z2 = *reinterpret_cast<const float4*>(zr + 2 * HID + lane * 4);
    float f[4];
    f[0] = b0 * elu1(z0.x) + b1 * elu1(z1.x) + b2 * elu1(z2.x);
    f[1] = b0 * elu1(z0.y) + b1 * elu1(z1.y) + b2 * elu1(z2.y);
    f[2] = b0 * elu1(z0.z) + b1 * elu1(z1.z) + b2 * elu1(z2.z);
    f[3] = b0 * elu1(z0.w) + b1 * elu1(z1.w) + b2 * elu1(z2.w);
    float po[OUTD];
#pragma unroll
    for (int o = 0; o < OUTD; o++) {
        po[o] = 0.f;
#pragma unroll
        for (int j = 0; j < 4; j++)
            po[o] += f[j] * sW[(lane * 4 + j) * OUTD + o];
    }
#pragma unroll
    for (int off = 16; off; off >>= 1)
#pragma unroll
        for (int o = 0; o < OUTD; o++)
            po[o] += __shfl_down_sync(0xffffffffu, po[o], off);
    if (lane == 0)
#pragma unroll
        for (int o = 0; o < OUTD; o++)
            out[(size_t)warp * OUTD + o] = po[o] + bout[o];
}

// ---------------- launch: multi-stream fork/join DAG ------------------------
extern "C" void kernel_launch(void* const* d_in, const int* in_sizes, int n_in,
                              void* d_out, int out_size)
{
    const float* features = (const float*)d_in[0];
    const float* W_fc     = (const float*)d_in[1];
    const float* b_fc     = (const float*)d_in[2];
    const float* W_src    = (const float*)d_in[3];
    const float* W_dst    = (const float*)d_in[4];
    const float* attn_l   = (const float*)d_in[5];
    const float* attn_r   = (const float*)d_in[6];
    const float* W_sem1   = (const float*)d_in[7];
    const float* b_sem1   = (const float*)d_in[8];
    const float* w_sem2   = (const float*)d_in[9];
    const float* W_out    = (const float*)d_in[10];
    const float* b_out    = (const float*)d_in[11];
    const int*   src_idx  = (const int*)d_in[12];
    const int*   dst_idx  = (const int*)d_in[13];
    float* out = (float*)d_out;

    float *h, *fs, *el, *er, *vd, *z, *w;
    int *cnt, *off, *pos, *ssrc;
    __nv_bfloat16 *bfc, *bpr, *bsm;
    cudaGetSymbolAddress((void**)&h,   d_h);
    cudaGetSymbolAddress((void**)&fs,  d_fs);
    cudaGetSymbolAddress((void**)&el,  d_el);
    cudaGetSymbolAddress((void**)&er,  d_er);
    cudaGetSymbolAddress((void**)&vd,  d_vd);
    cudaGetSymbolAddress((void**)&z,   d_z);
    cudaGetSymbolAddress((void**)&w,   d_w);
    cudaGetSymbolAddress((void**)&cnt, d_cnt);
    cudaGetSymbolAddress((void**)&off, d_off);
    cudaGetSymbolAddress((void**)&pos, d_pos);
    cudaGetSymbolAddress((void**)&ssrc,d_ssrc);
    cudaGetSymbolAddress((void**)&bfc, d_Bfc);
    cudaGetSymbolAddress((void**)&bpr, d_Bpr);
    cudaGetSymbolAddress((void**)&bsm, d_Bsm);

    // streams/events created once (host-side objects; no device allocation)
    static cudaStream_t s2 = nullptr, s3 = nullptr;
    static cudaEvent_t ev0 = nullptr, evCsr = nullptr, evH = nullptr, evEr = nullptr;
    if (!s2) {
        cudaStreamCreateWithFlags(&s2, cudaStreamNonBlocking);
        cudaStreamCreateWithFlags(&s3, cudaStreamNonBlocking);
        cudaEventCreateWithFlags(&ev0,   cudaEventDisableTiming);
        cudaEventCreateWithFlags(&evCsr, cudaEventDisableTiming);
        cudaEventCreateWithFlags(&evH,   cudaEventDisableTiming);
        cudaEventCreateWithFlags(&evEr,  cudaEventDisableTiming);
    }

    const int MT = (NN + 127) / 128;

    // fork s2 off the main (capture) stream
    cudaEventRecord(ev0, 0);
    cudaStreamWaitEvent(s2, ev0, 0);

    // --- stream s2: CSR build (independent of GEMMs) ---
    cudaMemsetAsync(cnt, 0, SEGS * sizeof(int), s2);
    count_kernel<<<(MM * EE + 255) / 256, 256, 0, s2>>>(dst_idx, cnt);
    scan_kernel<<<1, SCAN_T, 0, s2>>>(cnt, off, pos);
    fill_kernel<<<(MM * EE + 255) / 256, 256, 0, s2>>>(src_idx, dst_idx, pos, ssrc);
    cudaEventRecord(evCsr, s2);

    // --- main stream: prep + fc GEMM ---
    prep_all<<<dim3((128 * F_IN + 255) / 256, 6), 256>>>(W_fc, W_src, W_sem1,
                                                         W_dst, attn_r);
    mgemm<<<dim3(MT, 1), 256>>>(features, bfc, b_fc, h,
                                nullptr, nullptr, nullptr, nullptr,
                                NN, F_IN, 0);
    cudaEventRecord(evH, 0);

    // --- stream s3: er (needs h only) overlaps proj GEMM ---
    cudaStreamWaitEvent(s3, evH, 0);
    er_kernel<<<(NN + 7) / 8, 256, 0, s3>>>(h, vd, er);
    cudaEventRecord(evEr, s3);

    // --- main stream: proj GEMMs (fused el) ---
    mgemm<<<dim3(MT, MM), 256>>>(h, bpr, nullptr, fs,
                                 attn_l, el, nullptr, nullptr,
                                 NN, HID, 1);

    // join: gather needs CSR + er + proj
    cudaStreamWaitEvent(0, evCsr, 0);
    cudaStreamWaitEvent(0, evEr, 0);
    gather_kernel<<<(SEGS + 7) / 8, 256>>>(ssrc, off, cnt, el, er, fs, z);

    // semantic: w = tanh(elu(z) @ W_sem1 + b_sem1) . w_sem2
    mgemm<<<dim3((NN * MM + 127) / 128, 1), 256>>>(z, bsm, b_sem1, nullptr,
                                 nullptr, nullptr, w_sem2, w,
                                 NN * MM, HID, 2);

    final_kernel<<<(NN + 7) / 8, 256>>>(w, z, W_out, b_out, out);
}

// round 15
// speedup vs baseline: 1.3834x; 1.0753x over previous
#include <cuda_runtime.h>
#include <cuda_bf16.h>
#include <cstdint>

#define NN   50000
#define F_IN 256
#define HID  128
#define NH   8
#define EE   800000
#define MM   3
#define OUTD 8
#define SEGS (MM * NN)
#define CK   32   // K-chunk
#define ASTR 40   // padded smem row stride (halves)

// ---------------- scratch (device globals; no allocation) ----------------
__device__ float d_h [NN * HID];
__device__ float d_fs[(size_t)MM * NN * HID];
__device__ float d_el[(size_t)MM * NN * NH];
__device__ float d_er[(size_t)MM * NN * NH];
__device__ float d_vd[MM * NH * HID];
__device__ float d_z [(size_t)NN * MM * HID];
__device__ float d_w [NN * MM];
__device__ int   d_cnt [SEGS];
__device__ int   d_off [SEGS];
__device__ int   d_pos [SEGS];
__device__ int   d_ssrc[MM * EE];
// B' transposed weights, [128][2K]: [n][0..K)=hi, [n][K..2K)=lo
__device__ __nv_bfloat16 d_Bfc[128 * 2 * F_IN];
__device__ __nv_bfloat16 d_Bpr[MM * 128 * 2 * HID];
__device__ __nv_bfloat16 d_Bsm[128 * 2 * HID];

__device__ __forceinline__ float elu1(float v)
{
    return v > 0.f ? v : (__expf(v) - 1.f);
}

__device__ __forceinline__ uint32_t smem_u32(const void* p) {
    uint32_t a;
    asm("{ .reg .u64 t; cvta.to.shared.u64 t, %1; cvt.u32.u64 %0, t; }"
        : "=r"(a) : "l"(p));
    return a;
}

// ---------------- unified prep: all weight splits + Vdst in ONE launch ------
// blockIdx.y: 0 = W_fc->d_Bfc (K=256); 1..3 = W_src[m]->d_Bpr (K=128);
//             4 = W_sem1->d_Bsm (K=128); 5 = vdst
__global__ void prep_all(const float* __restrict__ W_fc,
                         const float* __restrict__ W_src,
                         const float* __restrict__ W_sem1,
                         const float* __restrict__ W_dst,
                         const float* __restrict__ ar)
{
    int y = blockIdx.y;
    int t = blockIdx.x * blockDim.x + threadIdx.x;
    if (y == 5) {
        if (t >= MM * NH * HID) return;
        int m = t / (NH * HID);
        int r = t - m * (NH * HID);
        int h = r / HID;
        int k = r - h * HID;
        const float* W = W_dst + ((size_t)m * HID + k) * HID + h * 16;
        const float* a = ar + (m * NH + h) * 16;
        float s = 0.f;
#pragma unroll
        for (int d = 0; d < 16; d++) s += W[d] * a[d];
        d_vd[(m * NH + h) * HID + k] = s;
        return;
    }
    const float* W;
    __nv_bfloat16* Bp;
    int K;
    if (y == 0)      { W = W_fc;   Bp = d_Bfc; K = F_IN; }
    else if (y <= 3) { int m = y - 1; W = W_src + (size_t)m * HID * HID;
                       Bp = d_Bpr + (size_t)m * 128 * 2 * HID; K = HID; }
    else             { W = W_sem1; Bp = d_Bsm; K = HID; }
    if (t >= 128 * K) return;
    int k = t >> 7;
    int n = t & 127;
    float v = W[(size_t)k * 128 + n];
    __nv_bfloat16 h = __float2bfloat16(v);
    __nv_bfloat16 l = __float2bfloat16(v - __bfloat162float(h));
    size_t base = (size_t)n * 2 * K;
    Bp[base + k]     = h;
    Bp[base + K + k] = l;
}

// ---------------- tensor-core GEMM via mma.sync, bf16 hi/lo split -----------
// D = Ah@Bh + Ah@Bl + Al@Bh  (fp32 accum); tile 128x128, 8 warps (2x4)
// mode 0: C = A@W + bias     mode 1: C = A@W ; el head-dots fused
// mode 2: A'=elu(A); wout = tanh(A'@W + bias) . w2  (no C store)
__global__ void __launch_bounds__(256) mgemm(
    const float* __restrict__ A, const __nv_bfloat16* __restrict__ B,
    const float* __restrict__ bias, float* __restrict__ C,
    const float* __restrict__ av, float* __restrict__ eo,
    const float* __restrict__ w2, float* __restrict__ wout,
    int Mrows, int K, int mode)
{
    __shared__ __nv_bfloat16 Ah[128 * ASTR];
    __shared__ __nv_bfloat16 Al[128 * ASTR];
    __shared__ __nv_bfloat16 Bh[128 * ASTR];
    __shared__ __nv_bfloat16 Bl[128 * ASTR];
    __shared__ float redbuf[128];

    const int tid = threadIdx.x;
    const int lane = tid & 31;
    const int wid = tid >> 5;
    const int warp_m = wid >> 2;      // 0..1 -> rows warp_m*64
    const int warp_n = wid & 3;       // 0..3 -> cols warp_n*32
    const int rowBase = blockIdx.x * 128;

    float cfr[4][4][4];
#pragma unroll
    for (int mt = 0; mt < 4; mt++)
#pragma unroll
        for (int nt = 0; nt < 4; nt++)
#pragma unroll
            for (int q = 0; q < 4; q++) cfr[mt][nt][q] = 0.f;

    // loader mapping: row = tid>>1, 16-wide half-chunk = (tid&1)*16
    const int lrow = tid >> 1;
    const int lcol = (tid & 1) * 16;
    const bool aok = (rowBase + lrow) < Mrows;
    const float* Arow = A + (size_t)(rowBase + lrow) * K;
    const __nv_bfloat16* Bh_row = B + (size_t)lrow * 2 * K;
    const __nv_bfloat16* Bl_row = Bh_row + K;

    const uint32_t ahb = smem_u32(Ah);
    const uint32_t alb = smem_u32(Al);
    const uint32_t bhb = smem_u32(Bh);
    const uint32_t blb = smem_u32(Bl);

    for (int kc = 0; kc < K; kc += CK) {
        // ---- load A chunk fp32 -> hi/lo bf16 ----
        {
            uint32_t* dh = reinterpret_cast<uint32_t*>(&Ah[lrow * ASTR + lcol]);
            uint32_t* dl = reinterpret_cast<uint32_t*>(&Al[lrow * ASTR + lcol]);
#pragma unroll
            for (int q = 0; q < 4; q++) {
                float4 v = aok ? *reinterpret_cast<const float4*>(Arow + kc + lcol + q * 4)
                               : make_float4(0.f, 0.f, 0.f, 0.f);
                if (mode == 2) { v.x = elu1(v.x); v.y = elu1(v.y); v.z = elu1(v.z); v.w = elu1(v.w); }
                __nv_bfloat16 h0 = __float2bfloat16(v.x);
                __nv_bfloat16 h1 = __float2bfloat16(v.y);
                __nv_bfloat16 h2 = __float2bfloat16(v.z);
                __nv_bfloat16 h3 = __float2bfloat16(v.w);
                __nv_bfloat16 l0 = __float2bfloat16(v.x - __bfloat162float(h0));
                __nv_bfloat16 l1 = __float2bfloat16(v.y - __bfloat162float(h1));
                __nv_bfloat16 l2 = __float2bfloat16(v.z - __bfloat162float(h2));
                __nv_bfloat16 l3 = __float2bfloat16(v.w - __bfloat162float(h3));
                __nv_bfloat162 hp0 = __halves2bfloat162(h0, h1);
                __nv_bfloat162 hp1 = __halves2bfloat162(h2, h3);
                __nv_bfloat162 lp0 = __halves2bfloat162(l0, l1);
                __nv_bfloat162 lp1 = __halves2bfloat162(l2, l3);
                dh[q * 2]     = *reinterpret_cast<uint32_t*>(&hp0);
                dh[q * 2 + 1] = *reinterpret_cast<uint32_t*>(&hp1);
                dl[q * 2]     = *reinterpret_cast<uint32_t*>(&lp0);
                dl[q * 2 + 1] = *reinterpret_cast<uint32_t*>(&lp1);
            }
        }
        // ---- load B hi/lo chunks (pre-split, straight copy) ----
        {
            const uint4* gh = reinterpret_cast<const uint4*>(Bh_row + kc + lcol);
            const uint4* gl = reinterpret_cast<const uint4*>(Bl_row + kc + lcol);
            uint4* dh = reinterpret_cast<uint4*>(&Bh[lrow * ASTR + lcol]);
            uint4* dl = reinterpret_cast<uint4*>(&Bl[lrow * ASTR + lcol]);
            dh[0] = gh[0]; dh[1] = gh[1];
            dl[0] = gl[0]; dl[1] = gl[1];
        }
        __syncthreads();

        // ---- 2 k-steps of 16 ----
#pragma unroll
        for (int ks = 0; ks < 2; ks++) {
            int k0 = ks * 16;
            int ra = warp_m * 64 + (lane & 15);
            int ka = k0 + (lane >> 4) * 8;
            int nb = warp_n * 32 + (lane & 7);
            int kb = k0 + ((lane >> 3) & 1) * 8;

            uint32_t ah[4][4], bh[4][2], bl[4][2];
#pragma unroll
            for (int mt = 0; mt < 4; mt++) {
                uint32_t addr = ahb + (uint32_t)((ra + mt * 16) * ASTR + ka) * 2u;
                asm volatile("ldmatrix.sync.aligned.m8n8.x4.shared.b16 {%0,%1,%2,%3}, [%4];"
                             : "=r"(ah[mt][0]), "=r"(ah[mt][1]), "=r"(ah[mt][2]), "=r"(ah[mt][3])
                             : "r"(addr));
            }
#pragma unroll
            for (int nt = 0; nt < 4; nt++) {
                uint32_t addr = bhb + (uint32_t)((nb + nt * 8) * ASTR + kb) * 2u;
                asm volatile("ldmatrix.sync.aligned.m8n8.x2.shared.b16 {%0,%1}, [%2];"
                             : "=r"(bh[nt][0]), "=r"(bh[nt][1]) : "r"(addr));
                uint32_t addr2 = blb + (uint32_t)((nb + nt * 8) * ASTR + kb) * 2u;
                asm volatile("ldmatrix.sync.aligned.m8n8.x2.shared.b16 {%0,%1}, [%2];"
                             : "=r"(bl[nt][0]), "=r"(bl[nt][1]) : "r"(addr2));
            }
#pragma unroll
            for (int mt = 0; mt < 4; mt++)
#pragma unroll
                for (int nt = 0; nt < 4; nt++) {
                    asm volatile(
                        "mma.sync.aligned.m16n8k16.row.col.f32.bf16.bf16.f32 "
                        "{%0,%1,%2,%3}, {%4,%5,%6,%7}, {%8,%9}, {%0,%1,%2,%3};"
                        : "+f"(cfr[mt][nt][0]), "+f"(cfr[mt][nt][1]),
                          "+f"(cfr[mt][nt][2]), "+f"(cfr[mt][nt][3])
                        : "r"(ah[mt][0]), "r"(ah[mt][1]), "r"(ah[mt][2]), "r"(ah[mt][3]),
                          "r"(bh[nt][0]), "r"(bh[nt][1]));
                    asm volatile(
                        "mma.sync.aligned.m16n8k16.row.col.f32.bf16.bf16.f32 "
                        "{%0,%1,%2,%3}, {%4,%5,%6,%7}, {%8,%9}, {%0,%1,%2,%3};"
                        : "+f"(cfr[mt][nt][0]), "+f"(cfr[mt][nt][1]),
                          "+f"(cfr[mt][nt][2]), "+f"(cfr[mt][nt][3])
                        : "r"(ah[mt][0]), "r"(ah[mt][1]), "r"(ah[mt][2]), "r"(ah[mt][3]),
                          "r"(bl[nt][0]), "r"(bl[nt][1]));
                }
            // A_lo frags after hi frags retire (register pressure)
            uint32_t al4[4][4];
#pragma unroll
            for (int mt = 0; mt < 4; mt++) {
                uint32_t addr = alb + (uint32_t)((ra + mt * 16) * ASTR + ka) * 2u;
                asm volatile("ldmatrix.sync.aligned.m8n8.x4.shared.b16 {%0,%1,%2,%3}, [%4];"
                             : "=r"(al4[mt][0]), "=r"(al4[mt][1]), "=r"(al4[mt][2]), "=r"(al4[mt][3])
                             : "r"(addr));
            }
#pragma unroll
            for (int mt = 0; mt < 4; mt++)
#pragma unroll
                for (int nt = 0; nt < 4; nt++) {
                    asm volatile(
                        "mma.sync.aligned.m16n8k16.row.col.f32.bf16.bf16.f32 "
                        "{%0,%1,%2,%3}, {%4,%5,%6,%7}, {%8,%9}, {%0,%1,%2,%3};"
                        : "+f"(cfr[mt][nt][0]), "+f"(cfr[mt][nt][1]),
                          "+f"(cfr[mt][nt][2]), "+f"(cfr[mt][nt][3])
                        : "r"(al4[mt][0]), "r"(al4[mt][1]), "r"(al4[mt][2]), "r"(al4[mt][3]),
                          "r"(bh[nt][0]), "r"(bh[nt][1]));
                }
        }
        __syncthreads();
    }

    // ---- epilogues ----
    const int g = lane >> 2, j = lane & 3;

    if (mode == 0 || mode == 1) {
#pragma unroll
        for (int mt = 0; mt < 4; mt++) {
            int r1 = rowBase + warp_m * 64 + mt * 16 + g;
            int r2 = r1 + 8;
#pragma unroll
            for (int nt = 0; nt < 4; nt++) {
                int c = warp_n * 32 + nt * 8 + j * 2;
                float b0 = 0.f, b1 = 0.f;
                if (mode == 0) { b0 = bias[c]; b1 = bias[c + 1]; }
                if (r1 < Mrows)
                    *reinterpret_cast<float2*>(C + (size_t)r1 * HID + c) =
                        make_float2(cfr[mt][nt][0] + b0, cfr[mt][nt][1] + b1);
                if (r2 < Mrows)
                    *reinterpret_cast<float2*>(C + (size_t)r2 * HID + c) =
                        make_float2(cfr[mt][nt][2] + b0, cfr[mt][nt][3] + b1);
            }
            if (mode == 1) {
                float p1[2] = {0.f, 0.f}, p2[2] = {0.f, 0.f};
#pragma unroll
                for (int nt = 0; nt < 4; nt++) {
                    int hl = nt >> 1;
                    int c = warp_n * 32 + nt * 8 + j * 2;
                    float a0 = av[c], a1 = av[c + 1];
                    p1[hl] += cfr[mt][nt][0] * a0 + cfr[mt][nt][1] * a1;
                    p2[hl] += cfr[mt][nt][2] * a0 + cfr[mt][nt][3] * a1;
                }
#pragma unroll
                for (int hl = 0; hl < 2; hl++) {
                    p1[hl] += __shfl_xor_sync(0xffffffffu, p1[hl], 1);
                    p1[hl] += __shfl_xor_sync(0xffffffffu, p1[hl], 2);
                    p2[hl] += __shfl_xor_sync(0xffffffffu, p2[hl], 1);
                    p2[hl] += __shfl_xor_sync(0xffffffffu, p2[hl], 2);
                }
                if (j == 0) {
                    int h0 = warp_n * 2;
                    if (r1 < Mrows) {
                        eo[(size_t)r1 * NH + h0]     = p1[0];
                        eo[(size_t)r1 * NH + h0 + 1] = p1[1];
                    }
                    if (r2 < Mrows) {
                        eo[(size_t)r2 * NH + h0]     = p2[0];
                        eo[(size_t)r2 * NH + h0 + 1] = p2[1];
                    }
                }
            }
        }
    } else {
        if (tid < 128) redbuf[tid] = 0.f;
        __syncthreads();
#pragma unroll
        for (int mt = 0; mt < 4; mt++) {
            float p1 = 0.f, p2 = 0.f;
#pragma unroll
            for (int nt = 0; nt < 4; nt++) {
                int c = warp_n * 32 + nt * 8 + j * 2;
                float b0 = bias[c], b1 = bias[c + 1];
                float w0 = w2[c], w1 = w2[c + 1];
                p1 += tanhf(cfr[mt][nt][0] + b0) * w0 + tanhf(cfr[mt][nt][1] + b1) * w1;
                p2 += tanhf(cfr[mt][nt][2] + b0) * w0 + tanhf(cfr[mt][nt][3] + b1) * w1;
            }
            p1 += __shfl_xor_sync(0xffffffffu, p1, 1);
            p1 += __shfl_xor_sync(0xffffffffu, p1, 2);
            p2 += __shfl_xor_sync(0xffffffffu, p2, 1);
            p2 += __shfl_xor_sync(0xffffffffu, p2, 2);
            if (j == 0) {
                atomicAdd(&redbuf[warp_m * 64 + mt * 16 + g], p1);
                atomicAdd(&redbuf[warp_m * 64 + mt * 16 + g + 8], p2);
            }
        }
        __syncthreads();
        if (tid < 128) {
            int r = rowBase + tid;
            if (r < Mrows) wout[r] = redbuf[tid];
        }
    }
}

// ---------------- er[m][n][h] = h_[n,:] . Vdst[m][h][:] (one warp per node) -
__global__ void er_kernel(const float* __restrict__ hfeat, const float* __restrict__ vd,
                          float* __restrict__ er)
{
    __shared__ float sV[MM * NH * HID];
    for (int i = threadIdx.x; i < MM * NH * HID; i += blockDim.x) sV[i] = vd[i];
    __syncthreads();
    int warp = (blockIdx.x * blockDim.x + threadIdx.x) >> 5;
    int lane = threadIdx.x & 31;
    if (warp >= NN) return;
    float4 hv = *reinterpret_cast<const float4*>(hfeat + (size_t)warp * HID + lane * 4);
#pragma unroll
    for (int m = 0; m < MM; m++) {
#pragma unroll
        for (int hh = 0; hh < NH; hh++) {
            float4 vv = *reinterpret_cast<const float4*>(&sV[(m * NH + hh) * HID + lane * 4]);
            float p = hv.x * vv.x + hv.y * vv.y + hv.z * vv.z + hv.w * vv.w;
            p += __shfl_xor_sync(0xffffffffu, p, 16);
            p += __shfl_xor_sync(0xffffffffu, p, 8);
            p += __shfl_xor_sync(0xffffffffu, p, 4);
            p += __shfl_xor_sync(0xffffffffu, p, 2);
            p += __shfl_xor_sync(0xffffffffu, p, 1);
            if (lane == 0) er[((size_t)m * NN + warp) * NH + hh] = p;
        }
    }
}

// ---------------- CSR build: count / scan / fill ----------------------------
__global__ void count_kernel(const int* __restrict__ dst, int* __restrict__ cnt)
{
    int t = blockIdx.x * blockDim.x + threadIdx.x;
    if (t >= MM * EE) return;
    int m = t / EE;
    atomicAdd(&cnt[m * NN + dst[t]], 1);
}

#define SCAN_T 1024
#define SCAN_CH ((SEGS + SCAN_T - 1) / SCAN_T)
__global__ void __launch_bounds__(SCAN_T) scan_kernel(const int* __restrict__ cnt,
                                                      int* __restrict__ off,
                                                      int* __restrict__ pos)
{
    __shared__ int sm[SCAN_T];
    int tid = threadIdx.x;
    int base = tid * SCAN_CH;
    int s = 0;
    for (int i = 0; i < SCAN_CH; i++) {
        int idx = base + i;
        if (idx < SEGS) s += cnt[idx];
    }
    sm[tid] = s;
    __syncthreads();
    for (int d = 1; d < SCAN_T; d <<= 1) {
        int v = (tid >= d) ? sm[tid - d] : 0;
        __syncthreads();
        sm[tid] += v;
        __syncthreads();
    }
    int run = sm[tid] - s;
    for (int i = 0; i < SCAN_CH; i++) {
        int idx = base + i;
        if (idx < SEGS) {
            off[idx] = run;
            pos[idx] = run;
            run += cnt[idx];
        }
    }
}

__global__ void fill_kernel(const int* __restrict__ src, const int* __restrict__ dst,
                            int* __restrict__ pos, int* __restrict__ ssrc)
{
    int t = blockIdx.x * blockDim.x + threadIdx.x;
    if (t >= MM * EE) return;
    int m = t / EE;
    int p = atomicAdd(&pos[m * NN + dst[t]], 1);
    ssrc[p] = src[t];
}

// ---------------- gather (per metapath m): single pass ----------------------
// out = (sum_i e_i * fs_i) / (sum_i e_i)
__global__ void gather_kernel(const int* __restrict__ ssrc,
                              const int* __restrict__ off, const int* __restrict__ cnt,
                              const float* __restrict__ el, const float* __restrict__ er,
                              const float* __restrict__ fs, float* __restrict__ z,
                              int m)
{
    int n = (blockIdx.x * blockDim.x + threadIdx.x) >> 5;
    int lane = threadIdx.x & 31;
    if (n >= NN) return;
    int seg = m * NN + n;
    int beg = off[seg];
    int num = cnt[seg];
    const float* elm = el + (size_t)m * NN * NH;
    const float* fsm = fs + (size_t)m * NN * HID;

    int h4 = lane >> 2;
    float er4 = er[(size_t)seg * NH + h4];

    float ssum0 = 0.f, ssum1 = 0.f;
    float4 acc0 = make_float4(0.f, 0.f, 0.f, 0.f);
    float4 acc1 = make_float4(0.f, 0.f, 0.f, 0.f);
    int it = 0;
    for (; it + 1 < num; it += 2) {
        int s0 = ssrc[beg + it];
        int s1 = ssrc[beg + it + 1];
        float v0 = elm[s0 * NH + h4] + er4;
        float v1 = elm[s1 * NH + h4] + er4;
        float4 f0 = *reinterpret_cast<const float4*>(fsm + (size_t)s0 * HID + lane * 4);
        float4 f1 = *reinterpret_cast<const float4*>(fsm + (size_t)s1 * HID + lane * 4);
        v0 = v0 > 0.f ? v0 : 0.2f * v0;
        v1 = v1 > 0.f ? v1 : 0.2f * v1;
        float e0 = __expf(v0);
        float e1 = __expf(v1);
        ssum0 += e0; ssum1 += e1;
        acc0.x += f0.x * e0; acc0.y += f0.y * e0; acc0.z += f0.z * e0; acc0.w += f0.w * e0;
        acc1.x += f1.x * e1; acc1.y += f1.y * e1; acc1.z += f1.z * e1; acc1.w += f1.w * e1;
    }
    if (it < num) {
        int s0 = ssrc[beg + it];
        float v0 = elm[s0 * NH + h4] + er4;
        float4 f0 = *reinterpret_cast<const float4*>(fsm + (size_t)s0 * HID + lane * 4);
        v0 = v0 > 0.f ? v0 : 0.2f * v0;
        float e0 = __expf(v0);
        ssum0 += e0;
        acc0.x += f0.x * e0; acc0.y += f0.y * e0; acc0.z += f0.z * e0; acc0.w += f0.w * e0;
    }
    float inv = 1.f / fmaxf(ssum0 + ssum1, 1e-9f);
    float4 o;
    o.x = (acc0.x + acc1.x) * inv;
    o.y = (acc0.y + acc1.y) * inv;
    o.z = (acc0.z + acc1.z) * inv;
    o.w = (acc0.w + acc1.w) * inv;
    *reinterpret_cast<float4*>(z + ((size_t)n * MM + m) * HID + lane * 4) = o;
}

// ---------------- final: beta softmax over w, elu(z) fuse, output GEMV ------
__global__ void final_kernel(const float* __restrict__ w, const float* __restrict__ z,
                             const float* __restrict__ Wout, const float* __restrict__ bout,
                             float* __restrict__ out)
{
    __shared__ float sW[HID * OUTD];
    for (int i = threadIdx.x; i < HID * OUTD; i += blockDim.x) sW[i] = Wout[i];
    __syncthreads();
    int warp = (blockIdx.x * blockDim.x + threadIdx.x) >> 5;
    int lane = threadIdx.x & 31;
    if (warp >= NN) return;
    float w0 = w[warp * 3 + 0], w1 = w[warp * 3 + 1], w2v = w[warp * 3 + 2];
    float mx = fmaxf(w0, fmaxf(w1, w2v));
    float e0 = __expf(w0 - mx), e1 = __expf(w1 - mx), e2 = __expf(w2v - mx);
    float inv = 1.f / (e0 + e1 + e2);
    float b0 = e0 * inv, b1 = e1 * inv, b2 = e2 * inv;
    const float* zr = z + (size_t)warp * (MM * HID);
    float4 z0 = *reinterpret_cast<const float4*>(zr + lane * 4);
    float4 z1 = *reinterpret_cast<const float4*>(zr + HID + lane * 4);
    float4 z2 = *reinterpret_cast<const float4*>(zr + 2 * HID + lane * 4);
    float f[4];
    f[0] = b0 * elu1(z0.x) + b1 * elu1(z1.x) + b2 * elu1(z2.x);
    f[1] = b0 * elu1(z0.y) + b1 * elu1(z1.y) + b2 * elu1(z2.y);
    f[2] = b0 * elu1(z0.z) + b1 * elu1(z1.z) + b2 * elu1(z2.z);
    f[3] = b0 * elu1(z0.w) + b1 * elu1(z1.w) + b2 * elu1(z2.w);
    float po[OUTD];
#pragma unroll
    for (int o = 0; o < OUTD; o++) {
        po[o] = 0.f;
#pragma unroll
        for (int j = 0; j < 4; j++)
            po[o] += f[j] * sW[(lane * 4 + j) * OUTD + o];
    }
#pragma unroll
    for (int off = 16; off; off >>= 1)
#pragma unroll
        for (int o = 0; o < OUTD; o++)
            po[o] += __shfl_down_sync(0xffffffffu, po[o], off);
    if (lane == 0)
#pragma unroll
        for (int o = 0; o < OUTD; o++)
            out[(size_t)warp * OUTD + o] = po[o] + bout[o];
}

// ---------------- launch: multi-stream pipelined DAG ------------------------
extern "C" void kernel_launch(void* const* d_in, const int* in_sizes, int n_in,
                              void* d_out, int out_size)
{
    const float* features = (const float*)d_in[0];
    const float* W_fc     = (const float*)d_in[1];
    const float* b_fc     = (const float*)d_in[2];
    const float* W_src    = (const float*)d_in[3];
    const float* W_dst    = (const float*)d_in[4];
    const float* attn_l   = (const float*)d_in[5];
    const float* attn_r   = (const float*)d_in[6];
    const float* W_sem1   = (const float*)d_in[7];
    const float* b_sem1   = (const float*)d_in[8];
    const float* w_sem2   = (const float*)d_in[9];
    const float* W_out    = (const float*)d_in[10];
    const float* b_out    = (const float*)d_in[11];
    const int*   src_idx  = (const int*)d_in[12];
    const int*   dst_idx  = (const int*)d_in[13];
    float* out = (float*)d_out;

    float *h, *fs, *el, *er, *vd, *z, *w;
    int *cnt, *off, *pos, *ssrc;
    __nv_bfloat16 *bfc, *bpr, *bsm;
    cudaGetSymbolAddress((void**)&h,   d_h);
    cudaGetSymbolAddress((void**)&fs,  d_fs);
    cudaGetSymbolAddress((void**)&el,  d_el);
    cudaGetSymbolAddress((void**)&er,  d_er);
    cudaGetSymbolAddress((void**)&vd,  d_vd);
    cudaGetSymbolAddress((void**)&z,   d_z);
    cudaGetSymbolAddress((void**)&w,   d_w);
    cudaGetSymbolAddress((void**)&cnt, d_cnt);
    cudaGetSymbolAddress((void**)&off, d_off);
    cudaGetSymbolAddress((void**)&pos, d_pos);
    cudaGetSymbolAddress((void**)&ssrc,d_ssrc);
    cudaGetSymbolAddress((void**)&bfc, d_Bfc);
    cudaGetSymbolAddress((void**)&bpr, d_Bpr);
    cudaGetSymbolAddress((void**)&bsm, d_Bsm);

    // streams/events created once (host-side objects; no device allocation)
    static cudaStream_t s2 = nullptr, s3 = nullptr;
    static cudaEvent_t ev0 = nullptr, evH = nullptr, evEr = nullptr, evG = nullptr;
    static cudaEvent_t evP[MM] = {nullptr, nullptr, nullptr};
    if (!s2) {
        cudaStreamCreateWithFlags(&s2, cudaStreamNonBlocking);
        cudaStreamCreateWithFlags(&s3, cudaStreamNonBlocking);
        cudaEventCreateWithFlags(&ev0,  cudaEventDisableTiming);
        cudaEventCreateWithFlags(&evH,  cudaEventDisableTiming);
        cudaEventCreateWithFlags(&evEr, cudaEventDisableTiming);
        cudaEventCreateWithFlags(&evG,  cudaEventDisableTiming);
        for (int m = 0; m < MM; m++)
            cudaEventCreateWithFlags(&evP[m], cudaEventDisableTiming);
    }

    const int MT = (NN + 127) / 128;

    // fork s2 off the main (capture) stream
    cudaEventRecord(ev0, 0);
    cudaStreamWaitEvent(s2, ev0, 0);

    // --- stream s2: CSR build (independent of GEMMs) ---
    cudaMemsetAsync(cnt, 0, SEGS * sizeof(int), s2);
    count_kernel<<<(MM * EE + 255) / 256, 256, 0, s2>>>(dst_idx, cnt);
    scan_kernel<<<1, SCAN_T, 0, s2>>>(cnt, off, pos);
    fill_kernel<<<(MM * EE + 255) / 256, 256, 0, s2>>>(src_idx, dst_idx, pos, ssrc);

    // --- main stream: prep + fc GEMM ---
    prep_all<<<dim3((128 * F_IN + 255) / 256, 6), 256>>>(W_fc, W_src, W_sem1,
                                                         W_dst, attn_r);
    mgemm<<<dim3(MT, 1), 256>>>(features, bfc, b_fc, h,
                                nullptr, nullptr, nullptr, nullptr,
                                NN, F_IN, 0);
    cudaEventRecord(evH, 0);

    // --- stream s3: er (needs h only) overlaps proj GEMMs ---
    cudaStreamWaitEvent(s3, evH, 0);
    er_kernel<<<(NN + 7) / 8, 256, 0, s3>>>(h, vd, er);
    cudaEventRecord(evEr, s3);

    // --- main stream: per-metapath proj GEMMs (fused el), each records evP[m]
    for (int m = 0; m < MM; m++) {
        mgemm<<<dim3(MT, 1), 256>>>(h, bpr + (size_t)m * 128 * 2 * HID, nullptr,
                                    fs + (size_t)m * NN * HID,
                                    attn_l + (size_t)m * HID,
                                    el + (size_t)m * NN * NH,
                                    nullptr, nullptr, NN, HID, 1);
        cudaEventRecord(evP[m], 0);
    }

    // --- stream s2: pipelined gathers (CSR already ordered on s2) ---
    cudaStreamWaitEvent(s2, evEr, 0);
    for (int m = 0; m < MM; m++) {
        cudaStreamWaitEvent(s2, evP[m], 0);
        gather_kernel<<<(NN + 7) / 8, 256, 0, s2>>>(ssrc, off, cnt, el, er, fs, z, m);
    }
    cudaEventRecord(evG, s2);

    // --- main stream: join, semantic GEMM, final ---
    cudaStreamWaitEvent(0, evG, 0);
    mgemm<<<dim3((NN * MM + 127) / 128, 1), 256>>>(z, bsm, b_sem1, nullptr,
                                 nullptr, nullptr, w_sem2, w,
                                 NN * MM, HID, 2);
    final_kernel<<<(NN + 7) / 8, 256>>>(w, z, W_out, b_out, out);
}